// round 2
// baseline (speedup 1.0000x reference)
#include <cuda_runtime.h>
#include <math.h>

#define NH 8
#define HD 64
#define SROW 512            // S*? no: row stride in elements of q/k/v = NH*HD
#define RS_QK 144           // Qpack/Kpack row stride (floats)
#define RS_V  72            // Vpack row stride (floats)
#define RS_P  72            // P row stride (floats)
#define OUT_ELEMS 2097152   // 4*1024*8*64
#define LSE_PER_RANK 8192   // 8*1024

__device__ __forceinline__ float tf32_rna(float x) {
    float y;
    asm("cvt.rna.tf32.f32 %0, %1;" : "=f"(y) : "f"(x));
    return y;
}

__device__ __forceinline__ void mma_tf32(float4& c,
    float a0, float a1, float a2, float a3, float b0, float b1)
{
    asm volatile(
        "mma.sync.aligned.m16n8k8.row.col.f32.tf32.tf32.f32 "
        "{%0,%1,%2,%3}, {%4,%5,%6,%7}, {%8,%9}, {%0,%1,%2,%3};\n"
        : "+f"(c.x), "+f"(c.y), "+f"(c.z), "+f"(c.w)
        : "r"(__float_as_uint(a0)), "r"(__float_as_uint(a1)),
          "r"(__float_as_uint(a2)), "r"(__float_as_uint(a3)),
          "r"(__float_as_uint(b0)), "r"(__float_as_uint(b1)));
}

__global__ __launch_bounds__(128) void zz_fa_tc_kernel(
    const float* __restrict__ q,
    const float* __restrict__ k,
    const float* __restrict__ v,
    float* __restrict__ out)
{
    extern __shared__ float sm[];
    float* Qpack = sm;                    // [64][144] {hi(c),hi(c+4),lo(c),lo(c+4)} per (kt,c)
    float* Kpack = Qpack + 64 * RS_QK;    // [64][144] same packing
    float* Vpack = Kpack + 64 * RS_QK;    // [64][72]  {V[kc8+c][n], V[kc8+c+4][n]} float2
    float* Pb    = Vpack + 64 * RS_V;     // [64][72]  P row-major

    const float4* Qp4 = reinterpret_cast<const float4*>(Qpack);
    const float4* Kp4 = reinterpret_cast<const float4*>(Kpack);
    const float2* Vp2 = reinterpret_cast<const float2*>(Vpack);
    float2*       Pp2 = reinterpret_cast<float2*>(Pb);

    const int qi = 63 - blockIdx.x;       // heavy tiles first
    const int h  = blockIdx.y;
    const int tid = threadIdx.x;
    const int w   = tid >> 5;             // warp 0..3, rows [w*16, w*16+16)
    const int lane = tid & 31;
    const int grp = lane >> 2;            // 0..7
    const int qd  = lane & 3;             // 0..3
    const int r0 = w * 16 + grp;
    const int r1 = r0 + 8;

    const int qbase = qi * 64;
    const float scale = 0.125f;

    // ---- pack Q once (scaled, hi/lo split) ----
    for (int idx = tid; idx < 64 * 16; idx += 128) {
        int row = idx >> 4;
        int d4  = (idx & 15) << 2;
        float4 qv = *reinterpret_cast<const float4*>(&q[(qbase + row) * SROW + h * HD + d4]);
        float vals[4] = {qv.x, qv.y, qv.z, qv.w};
#pragma unroll
        for (int j = 0; j < 4; j++) {
            int d = d4 + j;
            float val = vals[j] * scale;
            float hi = tf32_rna(val);
            float lo = tf32_rna(val - hi);
            int base = row * RS_QK + (d >> 3) * 16 + (d & 3) * 4 + ((d >> 2) & 1);
            Qpack[base]     = hi;
            Qpack[base + 2] = lo;
        }
    }

    float4 oacc[8];
    float m0 = -INFINITY, m1 = -INFINITY, l0 = 0.f, l1 = 0.f;
#pragma unroll
    for (int i = 0; i < 8; i++) oacc[i] = make_float4(0.f, 0.f, 0.f, 0.f);

    for (int jt = 0; jt <= qi; ++jt) {
        __syncthreads();                  // prev iter readers of Kpack/Vpack done
        const int kb = jt * 64;
        // ---- pack K (hi/lo) and V (rna) tiles ----
        for (int idx = tid; idx < 64 * 16; idx += 128) {
            int row = idx >> 4;
            int d4  = (idx & 15) << 2;
            int g = (kb + row) * SROW + h * HD + d4;
            float4 kv = *reinterpret_cast<const float4*>(&k[g]);
            float4 vv = *reinterpret_cast<const float4*>(&v[g]);
            float ka[4] = {kv.x, kv.y, kv.z, kv.w};
            float va[4] = {vv.x, vv.y, vv.z, vv.w};
#pragma unroll
            for (int j = 0; j < 4; j++) {
                int d = d4 + j;
                float hi = tf32_rna(ka[j]);
                float lo = tf32_rna(ka[j] - hi);
                int base = row * RS_QK + (d >> 3) * 16 + (d & 3) * 4 + ((d >> 2) & 1);
                Kpack[base]     = hi;
                Kpack[base + 2] = lo;
                // V: contraction dim = row (key pos), n = d
                Vpack[d * RS_V + (row >> 3) * 8 + (row & 3) * 2 + ((row >> 2) & 1)] = tf32_rna(va[j]);
            }
        }
        __syncthreads();

        // ---- S = Q K^T via 3xTF32 ----
        float4 sacc[8];
#pragma unroll
        for (int i = 0; i < 8; i++) sacc[i] = make_float4(0.f, 0.f, 0.f, 0.f);

#pragma unroll
        for (int kt = 0; kt < 8; kt++) {
            float4 qa = Qp4[r0 * 36 + kt * 4 + qd];   // {a0h,a2h,a0l,a2l}
            float4 qb = Qp4[r1 * 36 + kt * 4 + qd];   // {a1h,a3h,a1l,a3l}
#pragma unroll
            for (int nt = 0; nt < 8; nt++) {
                float4 kf = Kp4[(nt * 8 + grp) * 36 + kt * 4 + qd]; // {b0h,b1h,b0l,b1l}
                mma_tf32(sacc[nt], qa.x, qb.x, qa.y, qb.y, kf.x, kf.y); // hi*hi
                mma_tf32(sacc[nt], qa.z, qb.z, qa.w, qb.w, kf.x, kf.y); // lo*hi
                mma_tf32(sacc[nt], qa.x, qb.x, qa.y, qb.y, kf.z, kf.w); // hi*lo
            }
        }

        // ---- causal mask on diagonal tile ----
        if (jt == qi) {
#pragma unroll
            for (int nt = 0; nt < 8; nt++) {
                int c0 = nt * 8 + 2 * qd;
                if (c0     > r0) sacc[nt].x = -INFINITY;
                if (c0 + 1 > r0) sacc[nt].y = -INFINITY;
                if (c0     > r1) sacc[nt].z = -INFINITY;
                if (c0 + 1 > r1) sacc[nt].w = -INFINITY;
            }
        }

        // ---- online softmax (rows r0 -> x,y ; r1 -> z,w) ----
        float mx0 = -INFINITY, mx1 = -INFINITY;
#pragma unroll
        for (int nt = 0; nt < 8; nt++) {
            mx0 = fmaxf(mx0, fmaxf(sacc[nt].x, sacc[nt].y));
            mx1 = fmaxf(mx1, fmaxf(sacc[nt].z, sacc[nt].w));
        }
        mx0 = fmaxf(mx0, __shfl_xor_sync(0xffffffffu, mx0, 1));
        mx0 = fmaxf(mx0, __shfl_xor_sync(0xffffffffu, mx0, 2));
        mx1 = fmaxf(mx1, __shfl_xor_sync(0xffffffffu, mx1, 1));
        mx1 = fmaxf(mx1, __shfl_xor_sync(0xffffffffu, mx1, 2));

        float mn0 = fmaxf(m0, mx0), mn1 = fmaxf(m1, mx1);
        float al0 = __expf(m0 - mn0), al1 = __expf(m1 - mn1);
        float rs0 = 0.f, rs1 = 0.f;
#pragma unroll
        for (int nt = 0; nt < 8; nt++) {
            float px = __expf(sacc[nt].x - mn0);
            float py = __expf(sacc[nt].y - mn0);
            float pz = __expf(sacc[nt].z - mn1);
            float pw = __expf(sacc[nt].w - mn1);
            rs0 += px + py;
            rs1 += pz + pw;
            Pp2[r0 * 36 + nt * 4 + qd] = make_float2(tf32_rna(px), tf32_rna(py));
            Pp2[r1 * 36 + nt * 4 + qd] = make_float2(tf32_rna(pz), tf32_rna(pw));
        }
        rs0 += __shfl_xor_sync(0xffffffffu, rs0, 1);
        rs0 += __shfl_xor_sync(0xffffffffu, rs0, 2);
        rs1 += __shfl_xor_sync(0xffffffffu, rs1, 1);
        rs1 += __shfl_xor_sync(0xffffffffu, rs1, 2);
        l0 = l0 * al0 + rs0;  m0 = mn0;
        l1 = l1 * al1 + rs1;  m1 = mn1;
#pragma unroll
        for (int i = 0; i < 8; i++) {
            oacc[i].x *= al0; oacc[i].y *= al0;
            oacc[i].z *= al1; oacc[i].w *= al1;
        }
        __syncwarp();  // P written by quad-mates, read below within warp

        // ---- O += P V (single tf32) ----
#pragma unroll
        for (int kc = 0; kc < 8; kc++) {
            float a0 = Pb[r0 * RS_P + kc * 8 + qd];
            float a2 = Pb[r0 * RS_P + kc * 8 + qd + 4];
            float a1 = Pb[r1 * RS_P + kc * 8 + qd];
            float a3 = Pb[r1 * RS_P + kc * 8 + qd + 4];
#pragma unroll
            for (int dt = 0; dt < 8; dt++) {
                float2 bf = Vp2[(dt * 8 + grp) * 36 + kc * 4 + qd];
                mma_tf32(oacc[dt], a0, a1, a2, a3, bf.x, bf.y);
            }
        }
    }

    // ---- epilogue: normalize + zigzag scatter ----
    float inv0 = 1.f / l0, inv1 = 1.f / l1;
    int sg0 = qbase + r0, sg1 = qbase + r1;
    int c0g = sg0 >> 9, c1g = sg1 >> 9;
    int rk0 = (c0g < 4) ? c0g : 7 - c0g;
    int sl0 = (c0g < 4) ? (sg0 & 511) : 512 + (sg0 & 511);
    int rk1 = (c1g < 4) ? c1g : 7 - c1g;
    int sl1 = (c1g < 4) ? (sg1 & 511) : 512 + (sg1 & 511);
    int ob0 = rk0 * 524288 + sl0 * 512 + h * 64;
    int ob1 = rk1 * 524288 + sl1 * 512 + h * 64;
#pragma unroll
    for (int dt = 0; dt < 8; dt++) {
        int d = dt * 8 + 2 * qd;
        *reinterpret_cast<float2*>(&out[ob0 + d]) =
            make_float2(oacc[dt].x * inv0, oacc[dt].y * inv0);
        *reinterpret_cast<float2*>(&out[ob1 + d]) =
            make_float2(oacc[dt].z * inv1, oacc[dt].w * inv1);
    }
    if (qd == 0) {
        out[OUT_ELEMS + rk0 * LSE_PER_RANK + h * 1024 + sl0] = m0 + logf(l0);
        out[OUT_ELEMS + rk1 * LSE_PER_RANK + h * 1024 + sl1] = m1 + logf(l1);
    }
}

extern "C" void kernel_launch(void* const* d_in, const int* in_sizes, int n_in,
                              void* d_out, int out_size)
{
    const float* q = (const float*)d_in[0];
    const float* k = (const float*)d_in[1];
    const float* v = (const float*)d_in[2];
    float* out = (float*)d_out;

    const int smem_bytes = (64 * RS_QK * 2 + 64 * RS_V + 64 * RS_P) * (int)sizeof(float); // 110592
    static int configured = 0;
    cudaFuncSetAttribute(zz_fa_tc_kernel, cudaFuncAttributeMaxDynamicSharedMemorySize, smem_bytes);
    (void)configured;

    dim3 grid(64, NH);
    zz_fa_tc_kernel<<<grid, 128, smem_bytes>>>(q, k, v, out);
}